// round 9
// baseline (speedup 1.0000x reference)
#include <cuda_runtime.h>
#include <cuda_fp16.h>
#include <cstdint>

#define NIMG 256
#define RROOM 32
#define WW 8
#define HH 6
#define MXY 72
#define PIX (MXY*MXY)
#define EMBD 6

__device__ __align__(16) unsigned g_X0h[NIMG*8*PIX];
__device__ __align__(16) unsigned g_XAh[NIMG*32*PIX];
__device__ __align__(16) unsigned g_XBh[NIMG*32*PIX];
__device__ float g_feat[NIMG*RROOM*64];
__device__ float g_S[NIMG*128];
__device__ float g_wt[122880];
__device__ __align__(16) uint2 g_wp[25088];  // conv5 @0 (6656), conv3A @6656, conv3B @15872

__device__ __forceinline__ unsigned f2h2(float lo, float hi) {
    __half2 h = __floats2half2_rn(lo, hi);
    return *reinterpret_cast<unsigned*>(&h);
}
__device__ __forceinline__ void mma_f16(float d[4], const unsigned a[4], unsigned b0, unsigned b1) {
    asm volatile("mma.sync.aligned.m16n8k16.row.col.f32.f16.f16.f32 "
        "{%0,%1,%2,%3},{%4,%5,%6,%7},{%8,%9},{%0,%1,%2,%3};"
        : "+f"(d[0]), "+f"(d[1]), "+f"(d[2]), "+f"(d[3])
        : "r"(a[0]), "r"(a[1]), "r"(a[2]), "r"(a[3]), "r"(b0), "r"(b1));
}
__device__ __forceinline__ uint32_t smem_u32(const void* p) {
    uint32_t a;
    asm("{ .reg .u64 t; cvta.to.shared.u64 t, %1; cvt.u32.u64 %0, t; }" : "=r"(a) : "l"(p));
    return a;
}
#define CP_COMMIT() asm volatile("cp.async.commit_group;" ::: "memory")
#define CP_WAIT0()  asm volatile("cp.async.wait_group 0;" ::: "memory")

// ---------------- prep ----------------
__global__ void k_prep(const float* __restrict__ w1, const float* __restrict__ w2,
                       const float* __restrict__ w3,
                       const float* __restrict__ wr1, const float* __restrict__ wr2,
                       const float* __restrict__ wf1, const float* __restrict__ wf2,
                       float* __restrict__ wt, uint2* __restrict__ wp) {
    int t0 = blockIdx.x * blockDim.x + threadIdx.x;
    int stride = gridDim.x * blockDim.x;
    for (int i = t0; i < 8192; i += stride)  { int c = i >> 7, o = i & 127; wt[i]         = wr1[o*64 + c]; }
    for (int i = t0; i < 16384; i += stride) { int c = i >> 7, o = i & 127; wt[8192 + i]  = wr2[o*128 + c]; }
    for (int i = t0; i < 32768; i += stride) { int c = i >> 8, o = i & 255; wt[24576 + i] = wf1[o*128 + c]; }
    for (int i = t0; i < 65536; i += stride) { int c = i >> 8, o = i & 255; wt[57344 + i] = wf2[o*256 + c]; }
    for (int i = t0; i < 6656; i += stride) {
        int lane = i & 31, rest = i >> 5;
        int o = rest & 7; rest >>= 3;
        int ks = rest % 13, cc = rest / 13;
        int gg = lane >> 2, tt = lane & 3;
        int oc = o*8 + gg, ic0 = cc*8 + 2*tt;
        int tap0 = 2*ks, tap1 = 2*ks + 1;
        uint2 pv;
        pv.x = f2h2(w1[oc*400 + ic0*25 + tap0], w1[oc*400 + (ic0+1)*25 + tap0]);
        pv.y = (tap1 < 25) ? f2h2(w1[oc*400 + ic0*25 + tap1], w1[oc*400 + (ic0+1)*25 + tap1]) : 0u;
        wp[i] = pv;
    }
    for (int i = t0; i < 9216; i += stride) {
        int lane = i & 31, rest = i >> 5;
        int o = rest & 7; rest >>= 3;
        int ks = rest % 9, cc = rest / 9;
        int gg = lane >> 2, tt = lane & 3;
        int oc = o*8 + gg;
        int icA = cc*16 + 2*tt, icB = cc*16 + 2*tt + 8;
        uint2 pv, qv;
        pv.x = f2h2(w2[oc*576 + icA*9 + ks], w2[oc*576 + (icA+1)*9 + ks]);
        pv.y = f2h2(w2[oc*576 + icB*9 + ks], w2[oc*576 + (icB+1)*9 + ks]);
        wp[6656 + i] = pv;
        qv.x = f2h2(w3[oc*576 + icA*9 + ks], w3[oc*576 + (icA+1)*9 + ks]);
        qv.y = f2h2(w3[oc*576 + icB*9 + ks], w3[oc*576 + (icB+1)*9 + ks]);
        wp[15872 + i] = qv;
    }
}

__global__ void k_build(const int* __restrict__ pos, const float* __restrict__ rt,
                        const float* __restrict__ emb, unsigned* __restrict__ X0h) {
    int n = blockIdx.y, q = blockIdx.x, t = threadIdx.x;
    __shared__ int s_px[RROOM], s_py[RROOM];
    __shared__ float s_emb[RROOM*EMBD];
    if (t < RROOM) { s_px[t] = pos[(n*RROOM+t)*2]; s_py[t] = pos[(n*RROOM+t)*2+1]; }
    if (t < RROOM*EMBD) s_emb[t] = emb[t];
    __syncthreads();
    int p0 = q * 1296, p1 = p0 + 1296;
    for (int pix = p0 + t; pix < p1; pix += blockDim.x) {
        int i = pix / MXY, j = pix % MXY;
        float acc[9], em[EMBD];
        #pragma unroll
        for (int c = 0; c < 9; c++) acc[c] = 0.f;
        #pragma unroll
        for (int e = 0; e < EMBD; e++) em[e] = 0.f;
        #pragma unroll 1
        for (int r = 0; r < RROOM; r++) {
            int w = i - s_px[r], h = j - s_py[r];
            if ((unsigned)w < (unsigned)WW && (unsigned)h < (unsigned)HH) {
                const float* rp = rt + (r*9)*(WW*HH) + w*HH + h;
                float m0 = rp[0];
                #pragma unroll
                for (int c = 0; c < 9; c++) acc[c] += rp[c*(WW*HH)];
                #pragma unroll
                for (int e = 0; e < EMBD; e++) em[e] += s_emb[r*EMBD+e] * m0;
            }
        }
        unsigned* xp = X0h + (size_t)n*8*PIX + pix;
        xp[0*PIX] = f2h2(acc[0], acc[1]);
        xp[1*PIX] = f2h2(acc[2], acc[3]);
        xp[2*PIX] = f2h2(acc[4], acc[5]);
        xp[3*PIX] = f2h2(acc[6], acc[7]);
        xp[4*PIX] = f2h2(acc[8], 1.0f);
        xp[5*PIX] = f2h2(em[0], em[1]);
        xp[6*PIX] = f2h2(em[2], em[3]);
        xp[7*PIX] = f2h2(em[4], em[5]);
    }
}

// ---------------------------------------------------------------------------
// conv3x3 64->64, ReLU. 4-row tile, 9 warps x 2 m16-tiles, Mt=2, 2 blocks/SM.
// Weights all resident (73.7KB); input double-buffered cp.async (14.6KB each).
// smem total 102912.
// ---------------------------------------------------------------------------
#define C3_B0 73728
#define C3_B1 88320
#define C3_TOT 102912
__global__ __launch_bounds__(288, 2)
void k_conv3_v3(const unsigned* __restrict__ in, const uint2* __restrict__ wp,
                const float* __restrict__ bias, unsigned* __restrict__ out) {
    extern __shared__ __align__(16) char smem[];
    uint32_t sb = smem_u32(smem);
    int t = threadIdx.x, warp = t >> 5, lane = t & 31;
    int g = lane >> 2, tig = lane & 3;
    int n = blockIdx.y, r0 = blockIdx.x * 4;
    const uint2* swf = (const uint2*)smem;
    const unsigned* inb = in + (size_t)n * 32 * PIX;

    float acc[2][8][4];
    #pragma unroll
    for (int a = 0; a < 2; a++)
        #pragma unroll
        for (int o = 0; o < 8; o++)
            #pragma unroll
            for (int k = 0; k < 4; k++) acc[a][o][k] = 0.f;

    unsigned axoff[2][2];
    #pragma unroll
    for (int t2 = 0; t2 < 2; t2++)
        #pragma unroll
        for (int gi = 0; gi < 2; gi++) {
            int p = warp*32 + t2*16 + g + gi*8;   // 0..287
            axoff[t2][gi] = tig*456 + (p/72)*76 + (p%72);
        }

    // input chunk: 8 pairs x 6 rows x 74 cols -> [pair*456 + rr*76 + cx]
    #define C3_LOAD(cq, abase) do { \
        const unsigned* srcb = inb + (size_t)(cq)*8*PIX; \
        _Pragma("unroll") \
        for (int jj = 0; jj < 13; jj++) { \
            int i = t + jj*288; \
            if (i < 3552) { \
                int pair = i / 444; int s = i - pair*444; \
                int rr = s / 74; int cx = s - rr*74; \
                int gr = r0 - 1 + rr, gc = cx - 1; \
                unsigned v = ((unsigned)gr < 72u && (unsigned)gc < 72u) ? 4u : 0u; \
                const unsigned* gp = srcb + (size_t)pair*PIX + (v ? (gr*72 + gc) : 0); \
                unsigned dst = (abase) + (unsigned)(pair*456 + rr*76 + cx)*4u; \
                asm volatile("cp.async.ca.shared.global [%0], [%1], 4, %2;" \
                             :: "r"(dst), "l"(gp), "r"(v) : "memory"); \
            } \
        } } while (0)

    // prologue: all weights (73728B = 4608 x 16B) + input chunk 0
    #pragma unroll
    for (int jj = 0; jj < 16; jj++) {
        int i = t + jj*288;
        unsigned dst = sb + (unsigned)i*16u;
        const char* src = (const char*)wp + (size_t)i*16;
        asm volatile("cp.async.cg.shared.global [%0], [%1], 16;" :: "r"(dst), "l"(src) : "memory");
    }
    C3_LOAD(0, sb + C3_B0);
    CP_COMMIT();
    CP_WAIT0();
    __syncthreads();

    #pragma unroll 1
    for (int cc = 0; cc < 4; cc++) {
        if (cc < 3) {
            C3_LOAD(cc+1, (cc & 1) ? (sb + C3_B0) : (sb + C3_B1));
            CP_COMMIT();
        }
        const unsigned* sx = (const unsigned*)(smem + ((cc & 1) ? C3_B1 : C3_B0));
        const uint2* wfc = swf + cc*2304;
        #pragma unroll
        for (int ks = 0; ks < 9; ks++) {
            const int off = (ks/3)*76 + (ks%3);
            unsigned av[2][4];
            #pragma unroll
            for (int t2 = 0; t2 < 2; t2++)
                #pragma unroll
                for (int gi = 0; gi < 2; gi++) {
                    av[t2][gi]     = sx[axoff[t2][gi] + off];
                    av[t2][2 + gi] = sx[axoff[t2][gi] + 4*456 + off];
                }
            #pragma unroll
            for (int o = 0; o < 8; o++) {
                uint2 b = wfc[ks*256 + o*32 + lane];
                mma_f16(acc[0][o], av[0], b.x, b.y);
                mma_f16(acc[1][o], av[1], b.x, b.y);
            }
        }
        if (cc < 3) {
            CP_WAIT0();
            __syncthreads();
        }
    }

    unsigned* outb = out + (size_t)n * 32 * PIX;
    #pragma unroll
    for (int o = 0; o < 8; o++) {
        int oc0 = o*8 + 2*tig;
        float bv0 = bias[oc0], bv1 = bias[oc0 + 1];
        #pragma unroll
        for (int t2 = 0; t2 < 2; t2++)
            #pragma unroll
            for (int gi = 0; gi < 2; gi++) {
                int p = warp*32 + t2*16 + g + gi*8;
                int gr = r0 + p/72, gc = p%72;
                float v0 = fmaxf(acc[t2][o][gi*2 + 0] + bv0, 0.f);
                float v1 = fmaxf(acc[t2][o][gi*2 + 1] + bv1, 0.f);
                outb[(size_t)(o*4 + tig) * PIX + gr*72 + gc] = f2h2(v0, v1);
            }
    }
    #undef C3_LOAD
}

// ---------------------------------------------------------------------------
// conv5x5 16->64, ReLU. 4-row tile, 9 warps x 2 m16-tiles, 2 blocks/SM.
// All weights (53.2KB) + whole 16-ic input slab (19.7KB) resident; one load.
// ---------------------------------------------------------------------------
#define C5_A 53248
#define C5_TOT 72960
__global__ __launch_bounds__(288, 2)
void k_conv5_v3(const unsigned* __restrict__ in, const uint2* __restrict__ wp,
                const float* __restrict__ bias, unsigned* __restrict__ out) {
    extern __shared__ __align__(16) char smem[];
    uint32_t sb = smem_u32(smem);
    int t = threadIdx.x, warp = t >> 5, lane = t & 31;
    int g = lane >> 2, tig = lane & 3;
    int n = blockIdx.y, r0 = blockIdx.x * 4;
    const uint2* swf = (const uint2*)smem;
    const unsigned* sx = (const unsigned*)(smem + C5_A);
    const unsigned* inb = in + (size_t)n * 8 * PIX;

    float acc[2][8][4];
    #pragma unroll
    for (int a = 0; a < 2; a++)
        #pragma unroll
        for (int o = 0; o < 8; o++)
            #pragma unroll
            for (int k = 0; k < 4; k++) acc[a][o][k] = 0.f;

    unsigned axoff[2][2];
    #pragma unroll
    for (int t2 = 0; t2 < 2; t2++)
        #pragma unroll
        for (int gi = 0; gi < 2; gi++) {
            int p = warp*32 + t2*16 + g + gi*8;
            axoff[t2][gi] = tig*616 + (p/72)*77 + (p%72);
        }

    // weights: 6656 uint2 = 3328 x 16B
    #pragma unroll
    for (int jj = 0; jj < 12; jj++) {
        int i = t + jj*288;
        if (i < 3328) {
            unsigned dst = sb + (unsigned)i*16u;
            const char* src = (const char*)wp + (size_t)i*16;
            asm volatile("cp.async.cg.shared.global [%0], [%1], 16;" :: "r"(dst), "l"(src) : "memory");
        }
    }
    // input: 8 pairs x 8 rows x 76 used cols (stride 77), halo 2
    #pragma unroll
    for (int jj = 0; jj < 17; jj++) {
        int i = t + jj*288;
        if (i < 4864) {
            int pair = i / 608; int s = i - pair*608;
            int rr = s / 76; int cx = s - rr*76;
            int gr = r0 - 2 + rr, gc = cx - 2;
            unsigned v = ((unsigned)gr < 72u && (unsigned)gc < 72u) ? 4u : 0u;
            const unsigned* gp = inb + (size_t)pair*PIX + (v ? (gr*72 + gc) : 0);
            unsigned dst = sb + C5_A + (unsigned)(pair*616 + rr*77 + cx)*4u;
            asm volatile("cp.async.ca.shared.global [%0], [%1], 4, %2;"
                         :: "r"(dst), "l"(gp), "r"(v) : "memory");
        }
    }
    CP_COMMIT();
    CP_WAIT0();
    __syncthreads();

    #pragma unroll 1
    for (int cc = 0; cc < 2; cc++) {
        const unsigned* sxc = sx + cc*4*616;
        const uint2* wfc = swf + cc*3328;
        #pragma unroll
        for (int ks = 0; ks < 13; ks++) {
            const int tap0 = 2*ks;
            const int tap1 = (2*ks + 1 < 25) ? (2*ks + 1) : 24;  // B zero at pad
            const int off0 = (tap0/5)*77 + (tap0%5);
            const int off1 = (tap1/5)*77 + (tap1%5);
            unsigned av[2][4];
            #pragma unroll
            for (int t2 = 0; t2 < 2; t2++)
                #pragma unroll
                for (int gi = 0; gi < 2; gi++) {
                    av[t2][gi]     = sxc[axoff[t2][gi] + off0];
                    av[t2][2 + gi] = sxc[axoff[t2][gi] + off1];
                }
            #pragma unroll
            for (int o = 0; o < 8; o++) {
                uint2 b = wfc[ks*256 + o*32 + lane];
                mma_f16(acc[0][o], av[0], b.x, b.y);
                mma_f16(acc[1][o], av[1], b.x, b.y);
            }
        }
    }

    unsigned* outb = out + (size_t)n * 32 * PIX;
    #pragma unroll
    for (int o = 0; o < 8; o++) {
        int oc0 = o*8 + 2*tig;
        float bv0 = bias[oc0], bv1 = bias[oc0 + 1];
        #pragma unroll
        for (int t2 = 0; t2 < 2; t2++)
            #pragma unroll
            for (int gi = 0; gi < 2; gi++) {
                int p = warp*32 + t2*16 + g + gi*8;
                int gr = r0 + p/72, gc = p%72;
                float v0 = fmaxf(acc[t2][o][gi*2 + 0] + bv0, 0.f);
                float v1 = fmaxf(acc[t2][o][gi*2 + 1] + bv1, 0.f);
                outb[(size_t)(o*4 + tig) * PIX + gr*72 + gc] = f2h2(v0, v1);
            }
    }
}

__global__ void k_feat(const unsigned* __restrict__ Xh, const float* __restrict__ rt,
                       const int* __restrict__ pos, float* __restrict__ feat) {
    int b = blockIdx.x, n = b >> 5, r = b & 31, c = threadIdx.x;
    __shared__ float s_rm[48];
    if (c < 48) s_rm[c] = rt[r*9*48 + c];
    __syncthreads();
    float rsum = 0.f;
    #pragma unroll
    for (int k = 0; k < 48; k++) rsum += s_rm[k];
    int px = pos[b*2], py = pos[b*2+1];
    const unsigned* xp = Xh + ((size_t)n*32 + (c >> 1))*PIX + px*72 + py;
    int hi = c & 1;
    float acc = 0.f;
    #pragma unroll
    for (int w = 0; w < WW; w++)
        #pragma unroll
        for (int h = 0; h < HH; h++) {
            unsigned u = xp[w*72 + h];
            __half2 hv = *reinterpret_cast<const __half2*>(&u);
            acc += s_rm[w*HH + h] * (hi ? __high2float(hv) : __low2float(hv));
        }
    feat[b*64 + c] = acc / rsum;
}

__global__ __launch_bounds__(128)
void k_room(const float* __restrict__ feat, const float* __restrict__ wt,
            const float* __restrict__ b1, const float* __restrict__ b2,
            float* __restrict__ S) {
    const float* w1t = wt;
    const float* w2t = wt + 8192;
    int n = blockIdx.x, o = threadIdx.x;
    __shared__ float s_f[4][64];
    __shared__ float s_h1[4][128];
    float accS = 0.f;
    float bb1 = b1[o], bb2 = b2[o];
    for (int rg = 0; rg < 8; rg++) {
        #pragma unroll
        for (int i = o; i < 256; i += 128) {
            int r = i >> 6, c = i & 63;
            s_f[r][c] = feat[(n*RROOM + rg*4 + r)*64 + c];
        }
        __syncthreads();
        float a0 = bb1, a1 = bb1, a2 = bb1, a3 = bb1;
        #pragma unroll
        for (int c = 0; c < 64; c++) {
            float wv = w1t[c*128 + o];
            a0 += wv * s_f[0][c]; a1 += wv * s_f[1][c];
            a2 += wv * s_f[2][c]; a3 += wv * s_f[3][c];
        }
        s_h1[0][o] = fmaxf(a0, 0.f); s_h1[1][o] = fmaxf(a1, 0.f);
        s_h1[2][o] = fmaxf(a2, 0.f); s_h1[3][o] = fmaxf(a3, 0.f);
        __syncthreads();
        float z0 = bb2, z1 = bb2, z2 = bb2, z3 = bb2;
        #pragma unroll
        for (int c = 0; c < 128; c++) {
            float wv = w2t[c*128 + o];
            z0 += wv * s_h1[0][c]; z1 += wv * s_h1[1][c];
            z2 += wv * s_h1[2][c]; z3 += wv * s_h1[3][c];
        }
        accS += fmaxf(z0, 0.f) + fmaxf(z1, 0.f) + fmaxf(z2, 0.f) + fmaxf(z3, 0.f);
        __syncthreads();
    }
    S[n*128 + o] = accS;
}

__global__ __launch_bounds__(256)
void k_fc(const float* __restrict__ S, const float* __restrict__ wt,
          const float* __restrict__ bf1, const float* __restrict__ bf2,
          float* __restrict__ out) {
    const float* wf1t = wt + 24576;
    const float* wf2t = wt + 57344;
    int n0 = blockIdx.x * 4, o = threadIdx.x;
    __shared__ float s_in[4][128];
    __shared__ float s_h[4][256];
    #pragma unroll
    for (int i = o; i < 512; i += 256) {
        int q = i >> 7, c = i & 127;
        s_in[q][c] = S[(n0 + q)*128 + c];
    }
    __syncthreads();
    float a0 = bf1[o], a1 = a0, a2 = a0, a3 = a0;
    #pragma unroll
    for (int c = 0; c < 128; c++) {
        float wv = wf1t[c*256 + o];
        a0 += wv * s_in[0][c]; a1 += wv * s_in[1][c];
        a2 += wv * s_in[2][c]; a3 += wv * s_in[3][c];
    }
    s_h[0][o] = fmaxf(a0, 0.f); s_h[1][o] = fmaxf(a1, 0.f);
    s_h[2][o] = fmaxf(a2, 0.f); s_h[3][o] = fmaxf(a3, 0.f);
    __syncthreads();
    float z0 = bf2[o], z1 = z0, z2 = z0, z3 = z0;
    #pragma unroll
    for (int c = 0; c < 256; c++) {
        float wv = wf2t[c*256 + o];
        z0 += wv * s_h[0][c]; z1 += wv * s_h[1][c];
        z2 += wv * s_h[2][c]; z3 += wv * s_h[3][c];
    }
    out[(n0 + 0)*256 + o] = z0;
    out[(n0 + 1)*256 + o] = z1;
    out[(n0 + 2)*256 + o] = z2;
    out[(n0 + 3)*256 + o] = z3;
}

extern "C" void kernel_launch(void* const* d_in, const int* in_sizes, int n_in,
                              void* d_out, int out_size) {
    const int*   pos = (const int*)d_in[0];
    const float* rt  = (const float*)d_in[1];
    const float* emb = (const float*)d_in[2];
    const float* w1  = (const float*)d_in[3];
    const float* b1  = (const float*)d_in[4];
    const float* w2  = (const float*)d_in[5];
    const float* b2  = (const float*)d_in[6];
    const float* w3  = (const float*)d_in[7];
    const float* b3  = (const float*)d_in[8];
    const float* wr1 = (const float*)d_in[9];
    const float* br1 = (const float*)d_in[10];
    const float* wr2 = (const float*)d_in[11];
    const float* br2 = (const float*)d_in[12];
    const float* wf1 = (const float*)d_in[13];
    const float* bf1 = (const float*)d_in[14];
    const float* wf2 = (const float*)d_in[15];
    const float* bf2 = (const float*)d_in[16];
    float* out = (float*)d_out;

    unsigned *X0h, *XAh, *XBh;
    float *feat, *S, *wt;
    uint2 *wpk;
    cudaGetSymbolAddress((void**)&X0h, g_X0h);
    cudaGetSymbolAddress((void**)&XAh, g_XAh);
    cudaGetSymbolAddress((void**)&XBh, g_XBh);
    cudaGetSymbolAddress((void**)&feat, g_feat);
    cudaGetSymbolAddress((void**)&S, g_S);
    cudaGetSymbolAddress((void**)&wt, g_wt);
    cudaGetSymbolAddress((void**)&wpk, g_wp);

    cudaFuncSetAttribute(k_conv3_v3, cudaFuncAttributeMaxDynamicSharedMemorySize, C3_TOT);
    cudaFuncSetAttribute(k_conv5_v3, cudaFuncAttributeMaxDynamicSharedMemorySize, C5_TOT);

    k_prep<<<96, 256>>>(w1, w2, w3, wr1, wr2, wf1, wf2, wt, wpk);
    k_build<<<dim3(4, NIMG), 256>>>(pos, rt, emb, X0h);
    k_conv5_v3<<<dim3(18, NIMG), 288, C5_TOT>>>(X0h, wpk, b1, XAh);
    k_conv3_v3<<<dim3(18, NIMG), 288, C3_TOT>>>(XAh, wpk + 6656, b2, XBh);
    k_conv3_v3<<<dim3(18, NIMG), 288, C3_TOT>>>(XBh, wpk + 15872, b3, XAh);
    k_feat<<<NIMG*RROOM, 64>>>(XAh, rt, pos, feat);
    k_room<<<NIMG, 128>>>(feat, wt, br1, br2, S);
    k_fc<<<NIMG/4, 256>>>(S, wt, bf1, bf2, out);
}

// round 11
// speedup vs baseline: 1.3590x; 1.3590x over previous
#include <cuda_runtime.h>
#include <cuda_fp16.h>
#include <cstdint>

#define NIMG 256
#define RROOM 32
#define WW 8
#define HH 6
#define MXY 72
#define PIX (MXY*MXY)
#define EMBD 6

__device__ __align__(16) unsigned g_X0h[NIMG*8*PIX];
__device__ __align__(16) unsigned g_XAh[NIMG*32*PIX];   // conv5 out, NCHW pair-major
__device__ __align__(16) unsigned g_XBh[NIMG*32*PIX];   // conv2 out, NHWC (32 half2/px)
__device__ float g_feat[NIMG*RROOM*64];
__device__ float g_S[NIMG*128];
__device__ float g_wt[122880];
__device__ __align__(16) uint2 g_wp[25088];  // conv5 @0, conv3A @6656, conv3B @15872

__device__ __forceinline__ unsigned f2h2(float lo, float hi) {
    __half2 h = __floats2half2_rn(lo, hi);
    return *reinterpret_cast<unsigned*>(&h);
}
__device__ __forceinline__ void mma_f16(float d[4], const unsigned a[4], unsigned b0, unsigned b1) {
    asm volatile("mma.sync.aligned.m16n8k16.row.col.f32.f16.f16.f32 "
        "{%0,%1,%2,%3},{%4,%5,%6,%7},{%8,%9},{%0,%1,%2,%3};"
        : "+f"(d[0]), "+f"(d[1]), "+f"(d[2]), "+f"(d[3])
        : "r"(a[0]), "r"(a[1]), "r"(a[2]), "r"(a[3]), "r"(b0), "r"(b1));
}
__device__ __forceinline__ uint32_t smem_u32(const void* p) {
    uint32_t a;
    asm("{ .reg .u64 t; cvta.to.shared.u64 t, %1; cvt.u32.u64 %0, t; }" : "=r"(a) : "l"(p));
    return a;
}
#define CP_COMMIT() asm volatile("cp.async.commit_group;" ::: "memory")
#define CP_WAIT0()  asm volatile("cp.async.wait_group 0;" ::: "memory")

__global__ void k_prep(const float* __restrict__ w1, const float* __restrict__ w2,
                       const float* __restrict__ w3,
                       const float* __restrict__ wr1, const float* __restrict__ wr2,
                       const float* __restrict__ wf1, const float* __restrict__ wf2,
                       float* __restrict__ wt, uint2* __restrict__ wp) {
    int t0 = blockIdx.x * blockDim.x + threadIdx.x;
    int stride = gridDim.x * blockDim.x;
    for (int i = t0; i < 8192; i += stride)  { int c = i >> 7, o = i & 127; wt[i]         = wr1[o*64 + c]; }
    for (int i = t0; i < 16384; i += stride) { int c = i >> 7, o = i & 127; wt[8192 + i]  = wr2[o*128 + c]; }
    for (int i = t0; i < 32768; i += stride) { int c = i >> 8, o = i & 255; wt[24576 + i] = wf1[o*128 + c]; }
    for (int i = t0; i < 65536; i += stride) { int c = i >> 8, o = i & 255; wt[57344 + i] = wf2[o*256 + c]; }
    for (int i = t0; i < 6656; i += stride) {
        int lane = i & 31, rest = i >> 5;
        int o = rest & 7; rest >>= 3;
        int ks = rest % 13, cc = rest / 13;
        int gg = lane >> 2, tt = lane & 3;
        int oc = o*8 + gg, ic0 = cc*8 + 2*tt;
        int tap0 = 2*ks, tap1 = 2*ks + 1;
        uint2 pv;
        pv.x = f2h2(w1[oc*400 + ic0*25 + tap0], w1[oc*400 + (ic0+1)*25 + tap0]);
        pv.y = (tap1 < 25) ? f2h2(w1[oc*400 + ic0*25 + tap1], w1[oc*400 + (ic0+1)*25 + tap1]) : 0u;
        wp[i] = pv;
    }
    for (int i = t0; i < 9216; i += stride) {
        int lane = i & 31, rest = i >> 5;
        int o = rest & 7; rest >>= 3;
        int ks = rest % 9, cc = rest / 9;
        int gg = lane >> 2, tt = lane & 3;
        int oc = o*8 + gg;
        int icA = cc*16 + 2*tt, icB = cc*16 + 2*tt + 8;
        uint2 pv, qv;
        pv.x = f2h2(w2[oc*576 + icA*9 + ks], w2[oc*576 + (icA+1)*9 + ks]);
        pv.y = f2h2(w2[oc*576 + icB*9 + ks], w2[oc*576 + (icB+1)*9 + ks]);
        wp[6656 + i] = pv;
        qv.x = f2h2(w3[oc*576 + icA*9 + ks], w3[oc*576 + (icA+1)*9 + ks]);
        qv.y = f2h2(w3[oc*576 + icB*9 + ks], w3[oc*576 + (icB+1)*9 + ks]);
        wp[15872 + i] = qv;
    }
}

__global__ void k_build(const int* __restrict__ pos, const float* __restrict__ rt,
                        const float* __restrict__ emb, unsigned* __restrict__ X0h) {
    int n = blockIdx.y, q = blockIdx.x, t = threadIdx.x;
    __shared__ int s_px[RROOM], s_py[RROOM];
    __shared__ float s_emb[RROOM*EMBD];
    if (t < RROOM) { s_px[t] = pos[(n*RROOM+t)*2]; s_py[t] = pos[(n*RROOM+t)*2+1]; }
    if (t < RROOM*EMBD) s_emb[t] = emb[t];
    __syncthreads();
    int p0 = q * 1296, p1 = p0 + 1296;
    for (int pix = p0 + t; pix < p1; pix += blockDim.x) {
        int i = pix / MXY, j = pix % MXY;
        float acc[9], em[EMBD];
        #pragma unroll
        for (int c = 0; c < 9; c++) acc[c] = 0.f;
        #pragma unroll
        for (int e = 0; e < EMBD; e++) em[e] = 0.f;
        #pragma unroll 1
        for (int r = 0; r < RROOM; r++) {
            int w = i - s_px[r], h = j - s_py[r];
            if ((unsigned)w < (unsigned)WW && (unsigned)h < (unsigned)HH) {
                const float* rp = rt + (r*9)*(WW*HH) + w*HH + h;
                float m0 = rp[0];
                #pragma unroll
                for (int c = 0; c < 9; c++) acc[c] += rp[c*(WW*HH)];
                #pragma unroll
                for (int e = 0; e < EMBD; e++) em[e] += s_emb[r*EMBD+e] * m0;
            }
        }
        unsigned* xp = X0h + (size_t)n*8*PIX + pix;
        xp[0*PIX] = f2h2(acc[0], acc[1]);
        xp[1*PIX] = f2h2(acc[2], acc[3]);
        xp[2*PIX] = f2h2(acc[4], acc[5]);
        xp[3*PIX] = f2h2(acc[6], acc[7]);
        xp[4*PIX] = f2h2(acc[8], 1.0f);
        xp[5*PIX] = f2h2(em[0], em[1]);
        xp[6*PIX] = f2h2(em[2], em[3]);
        xp[7*PIX] = f2h2(em[4], em[5]);
    }
}

// conv3 64->64 (layer 2), ReLU. Mt=3 kernel; epilogue stores NHWC.
#define C3_B0 73728
#define C3_B1 98048
#define C3_TOT 122368
__global__ __launch_bounds__(384, 1)
void k_conv3_v2(const unsigned* __restrict__ in, const uint2* __restrict__ wp,
                const float* __restrict__ bias, unsigned* __restrict__ out) {
    extern __shared__ __align__(16) char smem[];
    uint32_t sb = smem_u32(smem);
    int t = threadIdx.x, warp = t >> 5, lane = t & 31;
    int g = lane >> 2, tig = lane & 3;
    int n = blockIdx.y, r0 = blockIdx.x * 8;
    const uint2* swf = (const uint2*)smem;
    const unsigned* inb = in + (size_t)n * 32 * PIX;

    float acc[3][8][4];
    #pragma unroll
    for (int a = 0; a < 3; a++)
        #pragma unroll
        for (int o = 0; o < 8; o++)
            #pragma unroll
            for (int k = 0; k < 4; k++) acc[a][o][k] = 0.f;

    unsigned axoff[3][2];
    #pragma unroll
    for (int t4 = 0; t4 < 3; t4++)
        #pragma unroll
        for (int gi = 0; gi < 2; gi++) {
            int p = warp*48 + t4*16 + g + gi*8;
            axoff[t4][gi] = tig*760 + (p/72)*76 + (p%72);
        }

    #define C3_LOAD(cq, abase) do { \
        const unsigned* srcb = inb + (size_t)(cq)*8*PIX; \
        _Pragma("unroll") \
        for (int jj = 0; jj < 16; jj++) { \
            int i = t + jj*384; \
            if (i < 5920) { \
                int pair = i / 740; int s = i - pair*740; \
                int rr = s / 74; int cx = s - rr*74; \
                int gr = r0 - 1 + rr, gc = cx - 1; \
                unsigned v = ((unsigned)gr < 72u && (unsigned)gc < 72u) ? 4u : 0u; \
                const unsigned* gp = srcb + (size_t)pair*PIX + (v ? (gr*72 + gc) : 0); \
                unsigned dst = (abase) + (unsigned)(pair*760 + rr*76 + cx)*4u; \
                asm volatile("cp.async.ca.shared.global [%0], [%1], 4, %2;" \
                             :: "r"(dst), "l"(gp), "r"(v) : "memory"); \
            } \
        } } while (0)

    #pragma unroll
    for (int jj = 0; jj < 12; jj++) {
        int i = t + jj*384;
        unsigned dst = sb + (unsigned)i*16u;
        const char* src = (const char*)wp + (size_t)i*16;
        asm volatile("cp.async.cg.shared.global [%0], [%1], 16;" :: "r"(dst), "l"(src) : "memory");
    }
    C3_LOAD(0, sb + C3_B0);
    CP_COMMIT();
    CP_WAIT0();
    __syncthreads();

    #pragma unroll 1
    for (int cc = 0; cc < 4; cc++) {
        if (cc < 3) {
            C3_LOAD(cc+1, (cc & 1) ? (sb + C3_B0) : (sb + C3_B1));
            CP_COMMIT();
        }
        const unsigned* sx = (const unsigned*)(smem + ((cc & 1) ? C3_B1 : C3_B0));
        const uint2* wfc = swf + cc*2304;
        #pragma unroll
        for (int ks = 0; ks < 9; ks++) {
            const int off = (ks/3)*76 + (ks%3);
            unsigned av[3][4];
            #pragma unroll
            for (int t4 = 0; t4 < 3; t4++)
                #pragma unroll
                for (int gi = 0; gi < 2; gi++) {
                    av[t4][gi]     = sx[axoff[t4][gi] + off];
                    av[t4][2 + gi] = sx[axoff[t4][gi] + 4*760 + off];
                }
            #pragma unroll
            for (int o = 0; o < 8; o++) {
                uint2 b = wfc[ks*256 + o*32 + lane];
                mma_f16(acc[0][o], av[0], b.x, b.y);
                mma_f16(acc[1][o], av[1], b.x, b.y);
                mma_f16(acc[2][o], av[2], b.x, b.y);
            }
        }
        if (cc < 3) {
            CP_WAIT0();
            __syncthreads();
        }
    }

    // NHWC epilogue: out[pixel*32 + oc_pair]
    unsigned* outb = out + (size_t)n * 32 * PIX;
    #pragma unroll
    for (int o = 0; o < 8; o++) {
        int oc0 = o*8 + 2*tig;
        float bv0 = bias[oc0], bv1 = bias[oc0 + 1];
        #pragma unroll
        for (int t4 = 0; t4 < 3; t4++)
            #pragma unroll
            for (int gi = 0; gi < 2; gi++) {
                int p = warp*48 + t4*16 + g + gi*8;
                int gr = r0 + p/72, gc = p%72;
                float v0 = fmaxf(acc[t4][o][gi*2 + 0] + bv0, 0.f);
                float v1 = fmaxf(acc[t4][o][gi*2 + 1] + bv1, 0.f);
                outb[(size_t)(gr*72 + gc)*32 + o*4 + tig] = f2h2(v0, v1);
            }
    }
    #undef C3_LOAD
}

// conv5 16->64, ReLU. Mt=3 kernel (NCHW-pair output).
#define C5_A 53248
#define C5_TOT 82432
__global__ __launch_bounds__(384, 1)
void k_conv5_v2(const unsigned* __restrict__ in, const uint2* __restrict__ wp,
                const float* __restrict__ bias, unsigned* __restrict__ out) {
    extern __shared__ __align__(16) char smem[];
    uint32_t sb = smem_u32(smem);
    int t = threadIdx.x, warp = t >> 5, lane = t & 31;
    int g = lane >> 2, tig = lane & 3;
    int n = blockIdx.y, r0 = blockIdx.x * 8;
    const uint2* swf = (const uint2*)smem;
    const unsigned* sx = (const unsigned*)(smem + C5_A);
    const unsigned* inb = in + (size_t)n * 8 * PIX;

    float acc[3][8][4];
    #pragma unroll
    for (int a = 0; a < 3; a++)
        #pragma unroll
        for (int o = 0; o < 8; o++)
            #pragma unroll
            for (int k = 0; k < 4; k++) acc[a][o][k] = 0.f;

    unsigned axoff[3][2];
    #pragma unroll
    for (int t4 = 0; t4 < 3; t4++)
        #pragma unroll
        for (int gi = 0; gi < 2; gi++) {
            int p = warp*48 + t4*16 + g + gi*8;
            axoff[t4][gi] = (p/72)*76 + (p%72);
        }

    #pragma unroll
    for (int jj = 0; jj < 9; jj++) {
        int i = t + jj*384;
        if (i < 3328) {
            unsigned dst = sb + (unsigned)i*16u;
            const char* src = (const char*)wp + (size_t)i*16;
            asm volatile("cp.async.cg.shared.global [%0], [%1], 16;" :: "r"(dst), "l"(src) : "memory");
        }
    }
    #pragma unroll
    for (int jj = 0; jj < 19; jj++) {
        int i = t + jj*384;
        if (i < 7296) {
            int pair = i / 912; int s = i - pair*912;
            int rr = s / 76; int cx = s - rr*76;
            int gr = r0 - 2 + rr, gc = cx - 2;
            unsigned v = ((unsigned)gr < 72u && (unsigned)gc < 72u) ? 4u : 0u;
            const unsigned* gp = inb + (size_t)pair*PIX + (v ? (gr*72 + gc) : 0);
            unsigned dst = sb + C5_A + (unsigned)i*4u;
            asm volatile("cp.async.ca.shared.global [%0], [%1], 4, %2;"
                         :: "r"(dst), "l"(gp), "r"(v) : "memory");
        }
    }
    CP_COMMIT();
    CP_WAIT0();
    __syncthreads();

    #pragma unroll 1
    for (int cc = 0; cc < 2; cc++) {
        const unsigned* sxc = sx + (cc*4 + tig)*912;
        const uint2* wfc = swf + cc*3328;
        #pragma unroll
        for (int ks = 0; ks < 13; ks++) {
            const int tap0 = 2*ks;
            const int tap1 = (2*ks + 1 < 25) ? (2*ks + 1) : 24;
            const int off0 = (tap0/5)*76 + (tap0%5);
            const int off1 = (tap1/5)*76 + (tap1%5);
            unsigned av[3][4];
            #pragma unroll
            for (int t4 = 0; t4 < 3; t4++)
                #pragma unroll
                for (int gi = 0; gi < 2; gi++) {
                    av[t4][gi]     = sxc[axoff[t4][gi] + off0];
                    av[t4][2 + gi] = sxc[axoff[t4][gi] + off1];
                }
            #pragma unroll
            for (int o = 0; o < 8; o++) {
                uint2 b = wfc[ks*256 + o*32 + lane];
                mma_f16(acc[0][o], av[0], b.x, b.y);
                mma_f16(acc[1][o], av[1], b.x, b.y);
                mma_f16(acc[2][o], av[2], b.x, b.y);
            }
        }
    }

    unsigned* outb = out + (size_t)n * 32 * PIX;
    #pragma unroll
    for (int o = 0; o < 8; o++) {
        int oc0 = o*8 + 2*tig;
        float bv0 = bias[oc0], bv1 = bias[oc0 + 1];
        #pragma unroll
        for (int t4 = 0; t4 < 3; t4++)
            #pragma unroll
            for (int gi = 0; gi < 2; gi++) {
                int p = warp*48 + t4*16 + g + gi*8;
                int gr = r0 + p/72, gc = p%72;
                float v0 = fmaxf(acc[t4][o][gi*2 + 0] + bv0, 0.f);
                float v1 = fmaxf(acc[t4][o][gi*2 + 1] + bv1, 0.f);
                outb[(size_t)(o*4 + tig) * PIX + gr*72 + gc] = f2h2(v0, v1);
            }
    }
}

// ---------------------------------------------------------------------------
// Layer 3 conv3 + feat, fused, room-window only. Pixel stride 36 words (144B,
// 16B-aligned for cp.async; banks 4g+tig -> near-conflict-free).
// ---------------------------------------------------------------------------
#define FW_B0 73728
#define FW_B1 119808
#define FW_TOT 165888
__global__ __launch_bounds__(384, 1)
void k_conv3_feat(const unsigned* __restrict__ xb, const uint2* __restrict__ wp,
                  const float* __restrict__ bias, const float* __restrict__ rt,
                  const int* __restrict__ pos, float* __restrict__ feat) {
    extern __shared__ __align__(16) char smem[];
    __shared__ float s_feat[4][64];
    __shared__ float s_wm[16][48];
    __shared__ float s_rsum[16];
    __shared__ int s_pos[16][2];
    uint32_t sb = smem_u32(smem);
    int t = threadIdx.x, warp = t >> 5, lane = t & 31;
    int g = lane >> 2, tig = lane & 3;
    int bx = blockIdx.x, n = bx >> 1, rbase = (bx & 1) * 16;
    const uint2* swf = (const uint2*)smem;
    const unsigned* xbn = xb + (size_t)n * 32 * PIX;

    for (int i = t; i < 16*48; i += 384) {
        int rr = i / 48, k = i % 48;
        s_wm[rr][k] = rt[(rbase + rr)*432 + k];
    }
    if (t < 32) s_pos[t >> 1][t & 1] = pos[(n*RROOM + rbase + (t >> 1))*2 + (t & 1)];
    if (t < 256) s_feat[t >> 6][t & 63] = 0.f;
    __syncthreads();
    if (t < 16) {
        float s = 0.f;
        #pragma unroll
        for (int k = 0; k < 48; k++) s += s_wm[t][k];
        s_rsum[t] = s;
    }

    // window gather: 4 rooms x 10 rows x 8 cols x 8 quads; pixel stride 36 wds
    #define FW_GATHER(ch, abase) do { \
        _Pragma("unroll") \
        for (int jj = 0; jj < 7; jj++) { \
            int i = t + jj*384; \
            if (i < 2560) { \
                int rr = i / 640; int rem = i - rr*640; \
                int wr2 = rem >> 6; int u = rem & 63; \
                int pc = u >> 3, q = u & 7; \
                int gr = s_pos[(ch)*4 + rr][0] - 1 + wr2; \
                int gc = s_pos[(ch)*4 + rr][1] - 1 + pc; \
                unsigned v = ((unsigned)gr < 72u && (unsigned)gc < 72u) ? 16u : 0u; \
                const unsigned* gp = xbn + (v ? ((size_t)(gr*72 + gc)*32 + q*4) : 0); \
                unsigned dst = (abase) + (unsigned)(rr*2880 + wr2*288 + pc*36 + q*4)*4u; \
                asm volatile("cp.async.cg.shared.global [%0], [%1], 16, %2;" \
                             :: "r"(dst), "l"(gp), "r"(v) : "memory"); \
            } \
        } } while (0)

    #pragma unroll
    for (int jj = 0; jj < 12; jj++) {
        int i = t + jj*384;
        unsigned dst = sb + (unsigned)i*16u;
        const char* src = (const char*)wp + (size_t)i*16;
        asm volatile("cp.async.cg.shared.global [%0], [%1], 16;" :: "r"(dst), "l"(src) : "memory");
    }
    FW_GATHER(0, sb + FW_B0);
    CP_COMMIT();
    CP_WAIT0();
    __syncthreads();

    int rw = warp & 3, mt = warp >> 2;        // room-in-chunk, m16-tile
    int p0 = mt*16 + g, p1 = p0 + 8;          // window pixels 0..47
    unsigned aw0 = (unsigned)(rw*2880 + (p0/6)*288 + (p0%6)*36 + tig);
    unsigned aw1 = (unsigned)(rw*2880 + (p1/6)*288 + (p1%6)*36 + tig);
    float bse[8], bso[8];
    #pragma unroll
    for (int o = 0; o < 8; o++) { bse[o] = bias[o*8 + 2*tig]; bso[o] = bias[o*8 + 2*tig + 1]; }

    #pragma unroll 1
    for (int ch = 0; ch < 4; ch++) {
        if (ch < 3) {
            FW_GATHER(ch+1, (ch & 1) ? (sb + FW_B0) : (sb + FW_B1));
            CP_COMMIT();
        }
        const unsigned* sx = (const unsigned*)(smem + ((ch & 1) ? FW_B1 : FW_B0));
        float acc[8][4];
        #pragma unroll
        for (int o = 0; o < 8; o++)
            #pragma unroll
            for (int k = 0; k < 4; k++) acc[o][k] = 0.f;

        #pragma unroll 1
        for (int cc = 0; cc < 4; cc++) {
            const uint2* wfc = swf + cc*2304;
            #pragma unroll
            for (int ks = 0; ks < 9; ks++) {
                const int off = (ks/3)*288 + (ks%3)*36;
                unsigned av[4];
                av[0] = sx[aw0 + off + cc*8];
                av[1] = sx[aw1 + off + cc*8];
                av[2] = sx[aw0 + off + cc*8 + 4];
                av[3] = sx[aw1 + off + cc*8 + 4];
                #pragma unroll
                for (int o = 0; o < 8; o++) {
                    uint2 b = wfc[ks*256 + o*32 + lane];
                    mma_f16(acc[o], av, b.x, b.y);
                }
            }
        }

        // fused feat: bias + ReLU + room-map weight, reduce over pixels
        float wm0 = s_wm[ch*4 + rw][p0];
        float wm1 = s_wm[ch*4 + rw][p1];
        #pragma unroll
        for (int o = 0; o < 8; o++) {
            float e = fmaxf(acc[o][0] + bse[o], 0.f)*wm0 + fmaxf(acc[o][2] + bse[o], 0.f)*wm1;
            float d2 = fmaxf(acc[o][1] + bso[o], 0.f)*wm0 + fmaxf(acc[o][3] + bso[o], 0.f)*wm1;
            e += __shfl_xor_sync(0xffffffffu, e, 16);
            e += __shfl_xor_sync(0xffffffffu, e, 8);
            e += __shfl_xor_sync(0xffffffffu, e, 4);
            d2 += __shfl_xor_sync(0xffffffffu, d2, 16);
            d2 += __shfl_xor_sync(0xffffffffu, d2, 8);
            d2 += __shfl_xor_sync(0xffffffffu, d2, 4);
            if (g == 0) {
                atomicAdd(&s_feat[rw][o*8 + 2*tig], e);
                atomicAdd(&s_feat[rw][o*8 + 2*tig + 1], d2);
            }
        }
        __syncthreads();
        if (t < 256) {
            int rr = t >> 6, oc = t & 63;
            feat[(n*RROOM + rbase + ch*4 + rr)*64 + oc] = s_feat[rr][oc] / s_rsum[ch*4 + rr];
            s_feat[rr][oc] = 0.f;
        }
        if (ch < 3) CP_WAIT0();
        __syncthreads();
    }
    #undef FW_GATHER
}

__global__ __launch_bounds__(128)
void k_room(const float* __restrict__ feat, const float* __restrict__ wt,
            const float* __restrict__ b1, const float* __restrict__ b2,
            float* __restrict__ S) {
    const float* w1t = wt;
    const float* w2t = wt + 8192;
    int n = blockIdx.x, o = threadIdx.x;
    __shared__ float s_f[4][64];
    __shared__ float s_h1[4][128];
    float accS = 0.f;
    float bb1 = b1[o], bb2 = b2[o];
    for (int rg = 0; rg < 8; rg++) {
        #pragma unroll
        for (int i = o; i < 256; i += 128) {
            int r = i >> 6, c = i & 63;
            s_f[r][c] = feat[(n*RROOM + rg*4 + r)*64 + c];
        }
        __syncthreads();
        float a0 = bb1, a1 = bb1, a2 = bb1, a3 = bb1;
        #pragma unroll
        for (int c = 0; c < 64; c++) {
            float wv = w1t[c*128 + o];
            a0 += wv * s_f[0][c]; a1 += wv * s_f[1][c];
            a2 += wv * s_f[2][c]; a3 += wv * s_f[3][c];
        }
        s_h1[0][o] = fmaxf(a0, 0.f); s_h1[1][o] = fmaxf(a1, 0.f);
        s_h1[2][o] = fmaxf(a2, 0.f); s_h1[3][o] = fmaxf(a3, 0.f);
        __syncthreads();
        float z0 = bb2, z1 = bb2, z2 = bb2, z3 = bb2;
        #pragma unroll
        for (int c = 0; c < 128; c++) {
            float wv = w2t[c*128 + o];
            z0 += wv * s_h1[0][c]; z1 += wv * s_h1[1][c];
            z2 += wv * s_h1[2][c]; z3 += wv * s_h1[3][c];
        }
        accS += fmaxf(z0, 0.f) + fmaxf(z1, 0.f) + fmaxf(z2, 0.f) + fmaxf(z3, 0.f);
        __syncthreads();
    }
    S[n*128 + o] = accS;
}

__global__ __launch_bounds__(256)
void k_fc(const float* __restrict__ S, const float* __restrict__ wt,
          const float* __restrict__ bf1, const float* __restrict__ bf2,
          float* __restrict__ out) {
    const float* wf1t = wt + 24576;
    const float* wf2t = wt + 57344;
    int n0 = blockIdx.x * 4, o = threadIdx.x;
    __shared__ float s_in[4][128];
    __shared__ float s_h[4][256];
    #pragma unroll
    for (int i = o; i < 512; i += 256) {
        int q = i >> 7, c = i & 127;
        s_in[q][c] = S[(n0 + q)*128 + c];
    }
    __syncthreads();
    float a0 = bf1[o], a1 = a0, a2 = a0, a3 = a0;
    #pragma unroll
    for (int c = 0; c < 128; c++) {
        float wv = wf1t[c*256 + o];
        a0 += wv * s_in[0][c]; a1 += wv * s_in[1][c];
        a2 += wv * s_in[2][c]; a3 += wv * s_in[3][c];
    }
    s_h[0][o] = fmaxf(a0, 0.f); s_h[1][o] = fmaxf(a1, 0.f);
    s_h[2][o] = fmaxf(a2, 0.f); s_h[3][o] = fmaxf(a3, 0.f);
    __syncthreads();
    float z0 = bf2[o], z1 = z0, z2 = z0, z3 = z0;
    #pragma unroll
    for (int c = 0; c < 256; c++) {
        float wv = wf2t[c*256 + o];
        z0 += wv * s_h[0][c]; z1 += wv * s_h[1][c];
        z2 += wv * s_h[2][c]; z3 += wv * s_h[3][c];
    }
    out[(n0 + 0)*256 + o] = z0;
    out[(n0 + 1)*256 + o] = z1;
    out[(n0 + 2)*256 + o] = z2;
    out[(n0 + 3)*256 + o] = z3;
}

extern "C" void kernel_launch(void* const* d_in, const int* in_sizes, int n_in,
                              void* d_out, int out_size) {
    const int*   pos = (const int*)d_in[0];
    const float* rt  = (const float*)d_in[1];
    const float* emb = (const float*)d_in[2];
    const float* w1  = (const float*)d_in[3];
    const float* b1  = (const float*)d_in[4];
    const float* w2  = (const float*)d_in[5];
    const float* b2  = (const float*)d_in[6];
    const float* w3  = (const float*)d_in[7];
    const float* b3  = (const float*)d_in[8];
    const float* wr1 = (const float*)d_in[9];
    const float* br1 = (const float*)d_in[10];
    const float* wr2 = (const float*)d_in[11];
    const float* br2 = (const float*)d_in[12];
    const float* wf1 = (const float*)d_in[13];
    const float* bf1 = (const float*)d_in[14];
    const float* wf2 = (const float*)d_in[15];
    const float* bf2 = (const float*)d_in[16];
    float* out = (float*)d_out;

    unsigned *X0h, *XAh, *XBh;
    float *feat, *S, *wt;
    uint2 *wpk;
    cudaGetSymbolAddress((void**)&X0h, g_X0h);
    cudaGetSymbolAddress((void**)&XAh, g_XAh);
    cudaGetSymbolAddress((void**)&XBh, g_XBh);
    cudaGetSymbolAddress((void**)&feat, g_feat);
    cudaGetSymbolAddress((void**)&S, g_S);
    cudaGetSymbolAddress((void**)&wt, g_wt);
    cudaGetSymbolAddress((void**)&wpk, g_wp);

    cudaFuncSetAttribute(k_conv3_v2, cudaFuncAttributeMaxDynamicSharedMemorySize, C3_TOT);
    cudaFuncSetAttribute(k_conv5_v2, cudaFuncAttributeMaxDynamicSharedMemorySize, C5_TOT);
    cudaFuncSetAttribute(k_conv3_feat, cudaFuncAttributeMaxDynamicSharedMemorySize, FW_TOT);

    k_prep<<<96, 256>>>(w1, w2, w3, wr1, wr2, wf1, wf2, wt, wpk);
    k_build<<<dim3(4, NIMG), 256>>>(pos, rt, emb, X0h);
    k_conv5_v2<<<dim3(9, NIMG), 384, C5_TOT>>>(X0h, wpk, b1, XAh);
    k_conv3_v2<<<dim3(9, NIMG), 384, C3_TOT>>>(XAh, wpk + 6656, b2, XBh);
    k_conv3_feat<<<NIMG*2, 384, FW_TOT>>>(XBh, wpk + 15872, b3, rt, pos, feat);
    k_room<<<NIMG, 128>>>(feat, wt, br1, br2, S);
    k_fc<<<NIMG/4, 256>>>(S, wt, bf1, bf2, out);
}